// round 4
// baseline (speedup 1.0000x reference)
#include <cuda_runtime.h>

// Row-wise L1 normalization: y[b,r,:] = x[b,r,:] / max(sum(x[b,r,:]), 1e-5)
// [16, 2048, 2048] fp32. One WARP per row, 32 lanes x 16 float4 = 2048 floats,
// fully register-resident. Each warp processes 8 CONTIGUOUS rows (64 KB
// sequential stream) for DRAM row-buffer locality; each CTA owns a contiguous
// 512 KB region. Warp-shuffle reduction only, no barriers.

#define ROW_LEN 2048
#define V4_PER_ROW (ROW_LEN / 4)       // 512
#define V4_PER_LANE (V4_PER_ROW / 32)  // 16
#define WARPS_PER_CTA 8
#define THREADS (WARPS_PER_CTA * 32)
#define ROWS_PER_WARP 8
#define N_ROWS (16 * 2048)             // 32768
#define GRID (N_ROWS / (WARPS_PER_CTA * ROWS_PER_WARP))  // 512

__global__ __launch_bounds__(THREADS, 3)
void rownorm_seq_kernel(const float4* __restrict__ in, float4* __restrict__ out) {
    const int warp = blockIdx.x * WARPS_PER_CTA + (threadIdx.x >> 5);
    const int lane = threadIdx.x & 31;
    // Contiguous block of rows for this warp.
    const int row0 = warp * ROWS_PER_WARP;

    #pragma unroll 1
    for (int r = 0; r < ROWS_PER_WARP; r++) {
        const long long base = (long long)(row0 + r) * V4_PER_ROW + lane;

        // Front-batched streaming loads (MLP = 16 LDG.128 per lane).
        float4 v[V4_PER_LANE];
        #pragma unroll
        for (int i = 0; i < V4_PER_LANE; i++)
            v[i] = __ldcs(&in[base + i * 32]);

        float s = 0.0f;
        #pragma unroll
        for (int i = 0; i < V4_PER_LANE; i++)
            s += (v[i].x + v[i].y) + (v[i].z + v[i].w);

        #pragma unroll
        for (int o = 16; o > 0; o >>= 1)
            s += __shfl_xor_sync(0xffffffffu, s, o);

        const float inv = 1.0f / fmaxf(s, 1e-5f);

        #pragma unroll
        for (int i = 0; i < V4_PER_LANE; i++) {
            float4 w = v[i];
            w.x *= inv; w.y *= inv; w.z *= inv; w.w *= inv;
            __stcs(&out[base + i * 32], w);
        }
    }
}

extern "C" void kernel_launch(void* const* d_in, const int* in_sizes, int n_in,
                              void* d_out, int out_size) {
    const float4* in = (const float4*)d_in[0];
    float4* out = (float4*)d_out;
    rownorm_seq_kernel<<<GRID, THREADS>>>(in, out);
}

// round 5
// speedup vs baseline: 1.1076x; 1.1076x over previous
#include <cuda_runtime.h>

// Row-wise L1 normalization: y[b,r,:] = x[b,r,:] / max(sum(x[b,r,:]), 1e-5)
// [16, 2048, 2048] fp32. One 64-thread CTA (2 warps) per row:
// 64 lanes x 8 float4 = 2048 floats, register-resident.
// MLP_p1=8 (halved vs warp-per-row) to cut cross-CTA L1tex-queue spread
// while higher occupancy keeps total in-flight loads high.

#define ROW_LEN 2048
#define V4_PER_ROW (ROW_LEN / 4)        // 512
#define THREADS 64
#define V4_PER_THREAD (V4_PER_ROW / THREADS)  // 8
#define N_ROWS (16 * 2048)              // 32768

__global__ __launch_bounds__(THREADS)
void rownorm_2w_kernel(const float4* __restrict__ in, float4* __restrict__ out) {
    const int t = threadIdx.x;
    const long long base = (long long)blockIdx.x * V4_PER_ROW + t;

    // Front-batched streaming loads: 8 independent LDG.128 per thread.
    float4 v[V4_PER_THREAD];
    #pragma unroll
    for (int i = 0; i < V4_PER_THREAD; i++)
        v[i] = __ldcs(&in[base + i * THREADS]);

    float s = 0.0f;
    #pragma unroll
    for (int i = 0; i < V4_PER_THREAD; i++)
        s += (v[i].x + v[i].y) + (v[i].z + v[i].w);

    // Warp reduction.
    #pragma unroll
    for (int o = 16; o > 0; o >>= 1)
        s += __shfl_xor_sync(0xffffffffu, s, o);

    // Combine the two warps via smem (2-warp barrier, 7-cyc floor).
    __shared__ float ws[2];
    if ((t & 31) == 0) ws[t >> 5] = s;
    __syncthreads();

    const float inv = 1.0f / fmaxf(ws[0] + ws[1], 1e-5f);

    #pragma unroll
    for (int i = 0; i < V4_PER_THREAD; i++) {
        float4 w = v[i];
        w.x *= inv; w.y *= inv; w.z *= inv; w.w *= inv;
        __stcs(&out[base + i * THREADS], w);
    }
}

extern "C" void kernel_launch(void* const* d_in, const int* in_sizes, int n_in,
                              void* d_out, int out_size) {
    const float4* in = (const float4*)d_in[0];
    float4* out = (float4*)d_out;
    rownorm_2w_kernel<<<N_ROWS, THREADS>>>(in, out);
}

// round 6
// speedup vs baseline: 1.1274x; 1.0179x over previous
#include <cuda_runtime.h>

// Row-wise L1 normalization: y[b,r,:] = x[b,r,:] / max(sum(x[b,r,:]), 1e-5)
// [16, 2048, 2048] fp32. 128-thread CTA = 2 warp-pairs, each pair owns one row.
// Per-thread: 8 float4 (MLP=8, empirically best). The two rows' phases
// interleave inside the CTA so one pair's barrier hides under the other's
// memory traffic. Barrier is pair-local via named barriers (bar.sync id, 64).

#define ROW_LEN 2048
#define V4_PER_ROW (ROW_LEN / 4)        // 512
#define THREADS 128
#define HALF 64
#define V4_PER_THREAD (V4_PER_ROW / HALF)  // 8
#define N_ROWS (16 * 2048)              // 32768
#define GRID (N_ROWS / 2)               // 16384

__global__ __launch_bounds__(THREADS)
void rownorm_2row_kernel(const float4* __restrict__ in, float4* __restrict__ out) {
    const int t = threadIdx.x;
    const int half = t >> 6;            // 0 or 1: which row this warp-pair owns
    const int ht = t & (HALF - 1);      // 0..63 within the pair
    const int row = blockIdx.x * 2 + half;
    const long long base = (long long)row * V4_PER_ROW + ht;

    // Front-batched streaming loads: 8 independent LDG.128 per thread.
    float4 v[V4_PER_THREAD];
    #pragma unroll
    for (int i = 0; i < V4_PER_THREAD; i++)
        v[i] = __ldcs(&in[base + i * HALF]);

    float s = 0.0f;
    #pragma unroll
    for (int i = 0; i < V4_PER_THREAD; i++)
        s += (v[i].x + v[i].y) + (v[i].z + v[i].w);

    // Warp reduction.
    #pragma unroll
    for (int o = 16; o > 0; o >>= 1)
        s += __shfl_xor_sync(0xffffffffu, s, o);

    // Pair-local combine of the two warps via named barrier (64 threads).
    __shared__ float ws[4];             // [half*2 + warp_in_pair]
    const int wip = (t >> 5) & 1;
    if ((t & 31) == 0) ws[half * 2 + wip] = s;
    // Named barrier per pair: id 1 and 2, 64 threads each.
    asm volatile("bar.sync %0, 64;" :: "r"(1 + half) : "memory");

    const float inv = 1.0f / fmaxf(ws[half * 2] + ws[half * 2 + 1], 1e-5f);

    #pragma unroll
    for (int i = 0; i < V4_PER_THREAD; i++) {
        float4 w = v[i];
        w.x *= inv; w.y *= inv; w.z *= inv; w.w *= inv;
        __stcs(&out[base + i * HALF], w);
    }
}

extern "C" void kernel_launch(void* const* d_in, const int* in_sizes, int n_in,
                              void* d_out, int out_size) {
    const float4* in = (const float4*)d_in[0];
    float4* out = (float4*)d_out;
    rownorm_2row_kernel<<<GRID, THREADS>>>(in, out);
}